// round 6
// baseline (speedup 1.0000x reference)
#include <cuda_runtime.h>
#include <math.h>
#include <stdint.h>

#define NN 50000
#define EE 800000
#define DD 128
#define HH 8
#define HIDDEN 512
#define BN_EPS 1e-5f
#define SLOPE 0.2f

// ---------------- scratch (static __device__ arrays; no allocation) ----------
__device__ float g_feat[(size_t)NN * DD];
__device__ float g_el[NN * HH];
__device__ float g_er[NN * HH];
__device__ float g_denom[NN * HH];
__device__ float g_agg[(size_t)NN * DD];
__device__ float g_mid[(size_t)NN * HIDDEN];
__device__ float g_stats[4 * DD];
__device__ float g_scale1[DD], g_shift1[DD];
__device__ float g_scale2[DD], g_shift2[DD];
// transposed + tf32-split weights: [N,K] K-major
__device__ float g_wT_hi[DD * DD],      g_wT_lo[DD * DD];        // W   (K=128,N=128)
__device__ float g_w1T_hi[HIDDEN * DD], g_w1T_lo[HIDDEN * DD];   // W1  (K=128,N=512)
__device__ float g_w2T_hi[DD * HIDDEN], g_w2T_lo[DD * HIDDEN];   // W2  (K=512,N=128)

// ---------------- helpers ----------------------------------------------------
__device__ __forceinline__ void split_tf32(float v, uint32_t& hi, uint32_t& lo) {
    asm("cvt.rna.tf32.f32 %0, %1;" : "=r"(hi) : "f"(v));
    float l = v - __uint_as_float(hi);
    asm("cvt.rna.tf32.f32 %0, %1;" : "=r"(lo) : "f"(l));
}

__device__ __forceinline__ void mma8(float* d, const uint32_t* a, const uint32_t* b) {
    asm volatile(
        "mma.sync.aligned.m16n8k8.row.col.f32.tf32.tf32.f32 "
        "{%0,%1,%2,%3}, {%4,%5,%6,%7}, {%8,%9}, {%0,%1,%2,%3};"
        : "+f"(d[0]), "+f"(d[1]), "+f"(d[2]), "+f"(d[3])
        : "r"(a[0]), "r"(a[1]), "r"(a[2]), "r"(a[3]), "r"(b[0]), "r"(b[1]));
}

// ---------------- utility ----------------------------------------------------
__global__ void zero_kernel(float* __restrict__ p, int n) {
    int i = blockIdx.x * blockDim.x + threadIdx.x;
    if (i < n) p[i] = 0.0f;
}

// transpose B[K,N] -> Bt[N,K] split into tf32 hi/lo
__global__ void prep_b_kernel(const float* __restrict__ B, float* __restrict__ th,
                              float* __restrict__ tl, int K, int N) {
    int i = blockIdx.x * blockDim.x + threadIdx.x;
    if (i >= N * K) return;
    int n = i / K, k = i - n * K;
    float v = B[(size_t)k * N + n];
    uint32_t h, l;
    split_tf32(v, h, l);
    th[i] = __uint_as_float(h);
    tl[i] = __uint_as_float(l);
}

// ---------------- 3xTF32 mma.sync GEMM: C[M,N] = A[M,K] @ Bt[N,K]^T ---------
// CTA tile 128x128, BK=32, 8 warps (2x4), warp tile 64x32.
// SMEM rows padded to 36 floats -> frag-load bank index == lane (conflict-free).
// ASCALE: BN fold on A columns. BIASR: relu(C + bias[n]).
#define SROW 36
template <bool ASCALE, bool BIASR>
__global__ void __launch_bounds__(256)
sgemm_mma(const float* __restrict__ A, const float* __restrict__ Bth,
          const float* __restrict__ Btl, float* __restrict__ C,
          int M, int N, int K,
          const float* __restrict__ ascale, const float* __restrict__ ashift,
          const float* __restrict__ bias)
{
    extern __shared__ float sm[];
    float* Ah = sm;                         // [128][36]
    float* Al = Ah + 128 * SROW;
    float* Bh = Al + 128 * SROW;            // [128][36], n-major
    float* Bl = Bh + 128 * SROW;

    const int tid = threadIdx.x;
    const int wid = tid >> 5, lane = tid & 31;
    const int gid = lane >> 2, tig = lane & 3;
    const int bm = blockIdx.y * 128, bn = blockIdx.x * 128;
    const int wm = (wid >> 2) * 64;         // warp row offset
    const int wn = (wid & 3) * 32;          // warp col offset

    float acc[4][4][4];
#pragma unroll
    for (int i = 0; i < 4; i++)
#pragma unroll
        for (int j = 0; j < 4; j++)
#pragma unroll
            for (int r = 0; r < 4; r++) acc[i][j][r] = 0.0f;

    for (int k0 = 0; k0 < K; k0 += 32) {
        // ---- fill SMEM: A and B 128x32 chunks, split hi/lo ----
#pragma unroll
        for (int j = 0; j < 4; j++) {
            int task = tid + j * 256;        // 0..1023
            int r = task >> 3, kq = (task & 7) * 4;
            // A (with optional BN fold)
            {
                int gr = bm + r;
                float4 v = make_float4(0.f, 0.f, 0.f, 0.f);
                if (gr < M) v = *(const float4*)(A + (size_t)gr * K + k0 + kq);
                if (ASCALE) {
                    int kc = k0 + kq;
                    v.x = fmaf(v.x, ascale[kc + 0], ashift[kc + 0]);
                    v.y = fmaf(v.y, ascale[kc + 1], ashift[kc + 1]);
                    v.z = fmaf(v.z, ascale[kc + 2], ashift[kc + 2]);
                    v.w = fmaf(v.w, ascale[kc + 3], ashift[kc + 3]);
                }
                uint4 h, l;
                split_tf32(v.x, h.x, l.x); split_tf32(v.y, h.y, l.y);
                split_tf32(v.z, h.z, l.z); split_tf32(v.w, h.w, l.w);
                *(uint4*)(Ah + r * SROW + kq) = h;
                *(uint4*)(Al + r * SROW + kq) = l;
            }
            // B (pre-split, straight copy; weight rows always in range)
            {
                float4 h = *(const float4*)(Bth + (size_t)(bn + r) * K + k0 + kq);
                float4 l = *(const float4*)(Btl + (size_t)(bn + r) * K + k0 + kq);
                *(float4*)(Bh + r * SROW + kq) = h;
                *(float4*)(Bl + r * SROW + kq) = l;
            }
        }
        __syncthreads();

        // ---- compute: 4 k-steps of 8 ----
#pragma unroll
        for (int ks = 0; ks < 4; ks++) {
            int kb = ks * 8;
            uint32_t bhf[4][2], blf[4][2];
#pragma unroll
            for (int nt = 0; nt < 4; nt++) {
                int n0 = (wn + nt * 8 + gid) * SROW + kb + tig;
                bhf[nt][0] = __float_as_uint(Bh[n0]);
                bhf[nt][1] = __float_as_uint(Bh[n0 + 4]);
                blf[nt][0] = __float_as_uint(Bl[n0]);
                blf[nt][1] = __float_as_uint(Bl[n0 + 4]);
            }
#pragma unroll
            for (int mt = 0; mt < 4; mt++) {
                int r0 = (wm + mt * 16 + gid) * SROW + kb + tig;
                int r1 = r0 + 8 * SROW;
                uint32_t ah[4], al[4];
                ah[0] = __float_as_uint(Ah[r0]);
                ah[1] = __float_as_uint(Ah[r1]);
                ah[2] = __float_as_uint(Ah[r0 + 4]);
                ah[3] = __float_as_uint(Ah[r1 + 4]);
                al[0] = __float_as_uint(Al[r0]);
                al[1] = __float_as_uint(Al[r1]);
                al[2] = __float_as_uint(Al[r0 + 4]);
                al[3] = __float_as_uint(Al[r1 + 4]);
#pragma unroll
                for (int nt = 0; nt < 4; nt++) {
                    mma8(acc[mt][nt], ah, bhf[nt]);
                    mma8(acc[mt][nt], ah, blf[nt]);
                    mma8(acc[mt][nt], al, bhf[nt]);
                }
            }
        }
        __syncthreads();
    }

    // ---- epilogue: register -> global (float2), fused bias+relu ----
#pragma unroll
    for (int mt = 0; mt < 4; mt++) {
        int r0 = bm + wm + mt * 16 + gid;
#pragma unroll
        for (int nt = 0; nt < 4; nt++) {
            int c0 = bn + wn + nt * 8 + tig * 2;
            float2 v0 = make_float2(acc[mt][nt][0], acc[mt][nt][1]);
            float2 v1 = make_float2(acc[mt][nt][2], acc[mt][nt][3]);
            if (BIASR) {
                float b0 = bias[c0], b1 = bias[c0 + 1];
                v0.x = fmaxf(v0.x + b0, 0.f); v0.y = fmaxf(v0.y + b1, 0.f);
                v1.x = fmaxf(v1.x + b0, 0.f); v1.y = fmaxf(v1.y + b1, 0.f);
            }
            if (r0 < M)     *(float2*)(C + (size_t)r0 * N + c0) = v0;
            if (r0 + 8 < M) *(float2*)(C + (size_t)(r0 + 8) * N + c0) = v1;
        }
    }
}

// ---------------- per-node attention logits (el, er) ------------------------
__global__ void eler_kernel(const float* __restrict__ feat,
                            const float* __restrict__ attn_l,
                            const float* __restrict__ attn_r,
                            float* __restrict__ el, float* __restrict__ er)
{
    int n = (blockIdx.x * blockDim.x + threadIdx.x) >> 5;
    int lane = threadIdx.x & 31;
    if (n >= NN) return;
    float4 v  = ((const float4*)(feat + (size_t)n * DD))[lane];
    float4 al = ((const float4*)attn_l)[lane];
    float4 ar = ((const float4*)attn_r)[lane];
    float pl = v.x * al.x + v.y * al.y + v.z * al.z + v.w * al.w;
    float pr = v.x * ar.x + v.y * ar.y + v.z * ar.z + v.w * ar.w;
    pl += __shfl_xor_sync(0xFFFFFFFFu, pl, 1);
    pl += __shfl_xor_sync(0xFFFFFFFFu, pl, 2);
    pr += __shfl_xor_sync(0xFFFFFFFFu, pr, 1);
    pr += __shfl_xor_sync(0xFFFFFFFFu, pr, 2);
    if ((lane & 3) == 0) {
        int h = lane >> 2;
        el[n * HH + h] = pl;
        er[n * HH + h] = pr;
    }
}

// ---------------- single edge pass -------------------------------------------
__global__ void edge_kernel(const int* __restrict__ src, const int* __restrict__ dst,
                            const float* __restrict__ el, const float* __restrict__ er,
                            float* __restrict__ denom,
                            const float* __restrict__ feat, float* __restrict__ agg)
{
    int e = (blockIdx.x * blockDim.x + threadIdx.x) >> 5;
    int lane = threadIdx.x & 31;
    if (e >= EE) return;
    int s = src[e], d = dst[e];
    int h = lane >> 2;
    float x = el[s * HH + h] + er[d * HH + h];
    x = (x > 0.0f) ? x : SLOPE * x;
    float w = expf(x);
    if ((lane & 3) == 0) atomicAdd(&denom[d * HH + h], w);
    float4 v = ((const float4*)(feat + (size_t)s * DD))[lane];
    float* out = agg + (size_t)d * DD + lane * 4;
    atomicAdd(out + 0, v.x * w);
    atomicAdd(out + 1, v.y * w);
    atomicAdd(out + 2, v.z * w);
    atomicAdd(out + 3, v.w * w);
}

// ---------------- fused normalize + BN1 column stats ------------------------
__global__ void div_stats_kernel(float* __restrict__ agg,
                                 const float* __restrict__ denom,
                                 float* __restrict__ sum, float* __restrict__ sumsq)
{
    int c = threadIdx.x;
    int hh = c >> 4;
    float s = 0.0f, s2 = 0.0f;
    for (int r = blockIdx.x; r < NN; r += gridDim.x) {
        float dn = denom[r * HH + hh];
        float v = agg[(size_t)r * DD + c] / dn;
        agg[(size_t)r * DD + c] = v;
        s += v;
        s2 += v * v;
    }
    atomicAdd(&sum[c], s);
    atomicAdd(&sumsq[c], s2);
}

__global__ void col_stats_kernel(const float* __restrict__ X, int M,
                                 float* __restrict__ sum, float* __restrict__ sumsq)
{
    int c = threadIdx.x;
    float s = 0.0f, s2 = 0.0f;
    for (int r = blockIdx.x; r < M; r += gridDim.x) {
        float v = X[(size_t)r * DD + c];
        s += v;
        s2 += v * v;
    }
    atomicAdd(&sum[c], s);
    atomicAdd(&sumsq[c], s2);
}

__global__ void bn_finalize_kernel(const float* __restrict__ sum, const float* __restrict__ sumsq,
                                   const float* __restrict__ gamma, const float* __restrict__ beta,
                                   float* __restrict__ scale, float* __restrict__ shift, float invM)
{
    int c = threadIdx.x;
    float mu = sum[c] * invM;
    float var = sumsq[c] * invM - mu * mu;
    float sc = gamma[c] * rsqrtf(var + BN_EPS);
    scale[c] = sc;
    shift[c] = beta[c] - mu * sc;
}

__global__ void bn_apply_kernel(float* __restrict__ X,
                                const float* __restrict__ scale, const float* __restrict__ shift)
{
    int i = blockIdx.x * blockDim.x + threadIdx.x;
    if (i < NN * DD) {
        int c = i & (DD - 1);
        X[i] = X[i] * scale[c] + shift[c];
    }
}

// ---------------- launch ----------------------------------------------------
#define SMEM_GEMM (4 * 128 * SROW * 4)   // 73728 bytes

extern "C" void kernel_launch(void* const* d_in, const int* in_sizes, int n_in,
                              void* d_out, int out_size)
{
    const float* x         = (const float*)d_in[0];
    const int*   src       = (const int*)  d_in[1];
    const int*   dst       = (const int*)  d_in[2];
    const float* W         = (const float*)d_in[3];
    const float* attn_l    = (const float*)d_in[4];
    const float* attn_r    = (const float*)d_in[5];
    const float* bn1_gamma = (const float*)d_in[7];
    const float* bn1_beta  = (const float*)d_in[8];
    const float* W1        = (const float*)d_in[9];
    const float* b1        = (const float*)d_in[10];
    const float* W2        = (const float*)d_in[11];
    const float* bn2_gamma = (const float*)d_in[13];
    const float* bn2_beta  = (const float*)d_in[14];
    float* out = (float*)d_out;

    float *p_feat, *p_el, *p_er, *p_denom, *p_agg, *p_mid, *p_stats;
    float *p_scale1, *p_shift1, *p_scale2, *p_shift2;
    float *p_wTh, *p_wTl, *p_w1Th, *p_w1Tl, *p_w2Th, *p_w2Tl;
    cudaGetSymbolAddress((void**)&p_feat,   g_feat);
    cudaGetSymbolAddress((void**)&p_el,     g_el);
    cudaGetSymbolAddress((void**)&p_er,     g_er);
    cudaGetSymbolAddress((void**)&p_denom,  g_denom);
    cudaGetSymbolAddress((void**)&p_agg,    g_agg);
    cudaGetSymbolAddress((void**)&p_mid,    g_mid);
    cudaGetSymbolAddress((void**)&p_stats,  g_stats);
    cudaGetSymbolAddress((void**)&p_scale1, g_scale1);
    cudaGetSymbolAddress((void**)&p_shift1, g_shift1);
    cudaGetSymbolAddress((void**)&p_scale2, g_scale2);
    cudaGetSymbolAddress((void**)&p_shift2, g_shift2);
    cudaGetSymbolAddress((void**)&p_wTh,  g_wT_hi);
    cudaGetSymbolAddress((void**)&p_wTl,  g_wT_lo);
    cudaGetSymbolAddress((void**)&p_w1Th, g_w1T_hi);
    cudaGetSymbolAddress((void**)&p_w1Tl, g_w1T_lo);
    cudaGetSymbolAddress((void**)&p_w2Th, g_w2T_hi);
    cudaGetSymbolAddress((void**)&p_w2Tl, g_w2T_lo);

    cudaFuncSetAttribute(sgemm_mma<false, false>,
                         cudaFuncAttributeMaxDynamicSharedMemorySize, SMEM_GEMM);
    cudaFuncSetAttribute(sgemm_mma<true, true>,
                         cudaFuncAttributeMaxDynamicSharedMemorySize, SMEM_GEMM);

    // weight prep: transpose + tf32 split
    prep_b_kernel<<<(DD * DD + 255) / 256, 256>>>(W, p_wTh, p_wTl, DD, DD);
    prep_b_kernel<<<(DD * HIDDEN + 255) / 256, 256>>>(W1, p_w1Th, p_w1Tl, DD, HIDDEN);
    prep_b_kernel<<<(HIDDEN * DD + 255) / 256, 256>>>(W2, p_w2Th, p_w2Tl, HIDDEN, DD);

    // zero accumulators
    zero_kernel<<<(NN * HH + 255) / 256, 256>>>(p_denom, NN * HH);
    zero_kernel<<<(NN * DD + 255) / 256, 256>>>(p_agg, NN * DD);
    zero_kernel<<<(4 * DD + 255) / 256, 256>>>(p_stats, 4 * DD);

    const int MT = (NN + 127) / 128;   // 391

    // feat = x @ W
    sgemm_mma<false, false><<<dim3(DD / 128, MT), 256, SMEM_GEMM>>>(
        x, p_wTh, p_wTl, p_feat, NN, DD, DD, nullptr, nullptr, nullptr);

    eler_kernel<<<(NN * 32 + 255) / 256, 256>>>(p_feat, attn_l, attn_r, p_el, p_er);

    edge_kernel<<<((size_t)EE * 32 + 255) / 256, 256>>>(src, dst, p_el, p_er,
                                                        p_denom, p_feat, p_agg);

    div_stats_kernel<<<1024, 128>>>(p_agg, p_denom, p_stats, p_stats + DD);
    bn_finalize_kernel<<<1, DD>>>(p_stats, p_stats + DD, bn1_gamma, bn1_beta,
                                  p_scale1, p_shift1, 1.0f / NN);

    // mid = relu(BN1(agg) @ W1 + b1)
    sgemm_mma<true, true><<<dim3(HIDDEN / 128, MT), 256, SMEM_GEMM>>>(
        p_agg, p_w1Th, p_w1Tl, p_mid, NN, HIDDEN, DD, p_scale1, p_shift1, b1);

    // out_pre = mid @ W2
    sgemm_mma<false, false><<<dim3(DD / 128, MT), 256, SMEM_GEMM>>>(
        p_mid, p_w2Th, p_w2Tl, out, NN, DD, HIDDEN, nullptr, nullptr, nullptr);

    col_stats_kernel<<<1024, 128>>>(out, NN, p_stats + 2 * DD, p_stats + 3 * DD);
    bn_finalize_kernel<<<1, DD>>>(p_stats + 2 * DD, p_stats + 3 * DD, bn2_gamma,
                                  bn2_beta, p_scale2, p_shift2, 1.0f / NN);
    bn_apply_kernel<<<(NN * DD + 255) / 256, 256>>>(out, p_scale2, p_shift2);
}

// round 7
// speedup vs baseline: 1.2720x; 1.2720x over previous
#include <cuda_runtime.h>
#include <math.h>
#include <stdint.h>

#define NN 50000
#define EE 800000
#define DD 128
#define HH 8
#define HIDDEN 512
#define BN_EPS 1e-5f
#define SLOPE 0.2f

// ---------------- scratch (static __device__ arrays; no allocation) ----------
__device__ float g_feat[(size_t)NN * DD];            // x @ W            25.6 MB
__device__ float g_el[NN * HH];
__device__ float g_er[NN * HH];
__device__ float g_agg[(size_t)NN * DD];             // normalized GAT output
__device__ float g_mid[(size_t)NN * HIDDEN];         // hidden activations 102 MB
__device__ float g_stats[4 * DD];
__device__ float g_scale1[DD], g_shift1[DD];
__device__ float g_scale2[DD], g_shift2[DD];
// CSR of incoming edges per dst node
__device__ int g_deg[NN];
__device__ int g_off[NN + 1];
__device__ int g_cursor[NN];
__device__ int g_csr_src[EE];

// ---------------- utility ---------------------------------------------------
__global__ void zero_f_kernel(float* __restrict__ p, int n) {
    int i = blockIdx.x * blockDim.x + threadIdx.x;
    if (i < n) p[i] = 0.0f;
}
__global__ void zero_i_kernel(int* __restrict__ p, int n) {
    int i = blockIdx.x * blockDim.x + threadIdx.x;
    if (i < n) p[i] = 0;
}

// ---------------- CSR build --------------------------------------------------
__global__ void hist_kernel(const int* __restrict__ dst, int* __restrict__ deg) {
    int e = blockIdx.x * blockDim.x + threadIdx.x;
    if (e < EE) atomicAdd(&deg[dst[e]], 1);
}

// single-block exclusive scan over 50000 degrees (1024 threads x 49 elems)
#define SCAN_T 1024
#define SCAN_PER 49
__global__ void __launch_bounds__(SCAN_T)
scan_kernel(const int* __restrict__ deg, int* __restrict__ off, int* __restrict__ cursor) {
    __shared__ int part[SCAN_T];
    int t = threadIdx.x;
    int base = t * SCAN_PER;
    int s = 0;
#pragma unroll
    for (int i = 0; i < SCAN_PER; i++) {
        int idx = base + i;
        if (idx < NN) s += deg[idx];
    }
    part[t] = s;
    __syncthreads();
    // inclusive Hillis-Steele scan
    for (int d = 1; d < SCAN_T; d <<= 1) {
        int add = (t >= d) ? part[t - d] : 0;
        __syncthreads();
        part[t] += add;
        __syncthreads();
    }
    int running = part[t] - s;      // exclusive prefix for this thread's chunk
#pragma unroll
    for (int i = 0; i < SCAN_PER; i++) {
        int idx = base + i;
        if (idx < NN) {
            off[idx] = running;
            cursor[idx] = running;
            running += deg[idx];
        }
    }
    if (t == SCAN_T - 1) off[NN] = running;   // == EE
}

__global__ void scatter_kernel(const int* __restrict__ src, const int* __restrict__ dst,
                               int* __restrict__ cursor, int* __restrict__ csr) {
    int e = blockIdx.x * blockDim.x + threadIdx.x;
    if (e >= EE) return;
    int pos = atomicAdd(&cursor[dst[e]], 1);
    csr[pos] = src[e];
}

// ---------------- SGEMM: C[M,N] = op(A[M,K] @ B[K,N]) ----------------------
// BM=128, BN=128, BK=16, 256 threads, 8x8 per thread. (R3-proven FFMA kernel)
template <bool ASCALE, bool BIASR>
__global__ void __launch_bounds__(256, 2)
sgemm128(const float* __restrict__ A, const float* __restrict__ B,
         float* __restrict__ C, int M, int N, int K,
         const float* __restrict__ ascale, const float* __restrict__ ashift,
         const float* __restrict__ bias)
{
    __shared__ float As[16][128];      // transposed: As[k][m]
    __shared__ float Bs[16][128];      // Bs[k][n]

    const int tid = threadIdx.x;
    const int bm = blockIdx.y * 128;
    const int bn = blockIdx.x * 128;
    const int tx = tid & 15;
    const int ty = tid >> 4;

    int ar[2], ac[2], br[2], bc[2];
#pragma unroll
    for (int j = 0; j < 2; j++) {
        int idx = tid * 2 + j;
        ar[j] = idx >> 2;
        ac[j] = (idx & 3) * 4;
        br[j] = idx >> 5;
        bc[j] = (idx & 31) * 4;
    }

    float4 pa[2], pb[2];

    auto loadA = [&](int k0) {
#pragma unroll
        for (int j = 0; j < 2; j++) {
            int grow = bm + ar[j];
            float4 v = make_float4(0.f, 0.f, 0.f, 0.f);
            if (grow < M)
                v = *(const float4*)(A + (size_t)grow * K + k0 + ac[j]);
            if (ASCALE) {
                int kc = k0 + ac[j];
                v.x = fmaf(v.x, ascale[kc + 0], ashift[kc + 0]);
                v.y = fmaf(v.y, ascale[kc + 1], ashift[kc + 1]);
                v.z = fmaf(v.z, ascale[kc + 2], ashift[kc + 2]);
                v.w = fmaf(v.w, ascale[kc + 3], ashift[kc + 3]);
            }
            pa[j] = v;
        }
    };
    auto loadB = [&](int k0) {
#pragma unroll
        for (int j = 0; j < 2; j++)
            pb[j] = *(const float4*)(B + (size_t)(k0 + br[j]) * N + bn + bc[j]);
    };

    float acc[8][8];
#pragma unroll
    for (int i = 0; i < 8; i++)
#pragma unroll
        for (int j = 0; j < 8; j++) acc[i][j] = 0.0f;

    loadA(0);
    loadB(0);

    for (int k0 = 0; k0 < K; k0 += 16) {
#pragma unroll
        for (int j = 0; j < 2; j++) {
            As[ac[j] + 0][ar[j]] = pa[j].x;
            As[ac[j] + 1][ar[j]] = pa[j].y;
            As[ac[j] + 2][ar[j]] = pa[j].z;
            As[ac[j] + 3][ar[j]] = pa[j].w;
            *(float4*)&Bs[br[j]][bc[j]] = pb[j];
        }
        __syncthreads();

        if (k0 + 16 < K) {
            loadA(k0 + 16);
            loadB(k0 + 16);
        }

#pragma unroll
        for (int kk = 0; kk < 16; kk++) {
            float4 a0 = *(const float4*)&As[kk][ty * 4];
            float4 a1 = *(const float4*)&As[kk][64 + ty * 4];
            float4 b0 = *(const float4*)&Bs[kk][tx * 4];
            float4 b1 = *(const float4*)&Bs[kk][64 + tx * 4];
            float a[8] = {a0.x, a0.y, a0.z, a0.w, a1.x, a1.y, a1.z, a1.w};
            float b[8] = {b0.x, b0.y, b0.z, b0.w, b1.x, b1.y, b1.z, b1.w};
#pragma unroll
            for (int i = 0; i < 8; i++)
#pragma unroll
                for (int j = 0; j < 8; j++)
                    acc[i][j] = fmaf(a[i], b[j], acc[i][j]);
        }
        __syncthreads();
    }

#pragma unroll
    for (int ri = 0; ri < 8; ri++) {
        int lr = (ri < 4) ? (ty * 4 + ri) : (64 + ty * 4 + (ri - 4));
        int gr = bm + lr;
        if (gr >= M) continue;
#pragma unroll
        for (int cf = 0; cf < 2; cf++) {
            int gc = bn + cf * 64 + tx * 4;
            float4 o;
            float* op = (float*)&o;
#pragma unroll
            for (int j = 0; j < 4; j++) {
                float v = acc[ri][cf * 4 + j];
                if (BIASR) v = fmaxf(v + bias[gc + j], 0.0f);
                op[j] = v;
            }
            *(float4*)(C + (size_t)gr * N + gc) = o;
        }
    }
}

// ---------------- per-node attention logits (el, er) ------------------------
__global__ void eler_kernel(const float* __restrict__ feat,
                            const float* __restrict__ attn_l,
                            const float* __restrict__ attn_r,
                            float* __restrict__ el, float* __restrict__ er)
{
    int n = (blockIdx.x * blockDim.x + threadIdx.x) >> 5;
    int lane = threadIdx.x & 31;
    if (n >= NN) return;
    float4 v  = ((const float4*)(feat + (size_t)n * DD))[lane];
    float4 al = ((const float4*)attn_l)[lane];
    float4 ar = ((const float4*)attn_r)[lane];
    float pl = v.x * al.x + v.y * al.y + v.z * al.z + v.w * al.w;
    float pr = v.x * ar.x + v.y * ar.y + v.z * ar.z + v.w * ar.w;
    pl += __shfl_xor_sync(0xFFFFFFFFu, pl, 1);
    pl += __shfl_xor_sync(0xFFFFFFFFu, pl, 2);
    pr += __shfl_xor_sync(0xFFFFFFFFu, pr, 1);
    pr += __shfl_xor_sync(0xFFFFFFFFu, pr, 2);
    if ((lane & 3) == 0) {
        int h = lane >> 2;
        el[n * HH + h] = pl;
        er[n * HH + h] = pr;
    }
}

// ---------------- warp-per-dst gather aggregation (no fp atomics) ------------
// lane l handles float4 at col 4l, head h=l/4. Walks the CSR in-edge list,
// accumulates un-normalized sum + weight sum in registers, writes normalized.
__global__ void agg_kernel(const int* __restrict__ off, const int* __restrict__ csr,
                           const float* __restrict__ el, const float* __restrict__ er,
                           const float* __restrict__ feat, float* __restrict__ agg)
{
    int d = (blockIdx.x * blockDim.x + threadIdx.x) >> 5;
    int lane = threadIdx.x & 31;
    if (d >= NN) return;
    int h = lane >> 2;
    float erv = er[d * HH + h];
    int i0 = off[d], i1 = off[d + 1];
    float4 acc = make_float4(0.f, 0.f, 0.f, 0.f);
    float wsum = 0.0f;
    for (int i = i0; i < i1; i++) {
        int s = __ldg(&csr[i]);
        float x = el[s * HH + h] + erv;
        x = (x > 0.0f) ? x : SLOPE * x;
        float w = __expf(x);
        wsum += w;
        float4 v = ((const float4*)(feat + (size_t)s * DD))[lane];
        acc.x = fmaf(w, v.x, acc.x);
        acc.y = fmaf(w, v.y, acc.y);
        acc.z = fmaf(w, v.z, acc.z);
        acc.w = fmaf(w, v.w, acc.w);
    }
    float4 o = make_float4(0.f, 0.f, 0.f, 0.f);
    if (i1 > i0) {
        float inv = 1.0f / wsum;
        o.x = acc.x * inv; o.y = acc.y * inv;
        o.z = acc.z * inv; o.w = acc.w * inv;
    }
    ((float4*)(agg + (size_t)d * DD))[lane] = o;
}

// ---------------- column statistics ------------------------------------------
__global__ void col_stats_kernel(const float* __restrict__ X, int M,
                                 float* __restrict__ sum, float* __restrict__ sumsq)
{
    int c = threadIdx.x;
    float s = 0.0f, s2 = 0.0f;
    for (int r = blockIdx.x; r < M; r += gridDim.x) {
        float v = X[(size_t)r * DD + c];
        s += v;
        s2 += v * v;
    }
    atomicAdd(&sum[c], s);
    atomicAdd(&sumsq[c], s2);
}

__global__ void bn_finalize_kernel(const float* __restrict__ sum, const float* __restrict__ sumsq,
                                   const float* __restrict__ gamma, const float* __restrict__ beta,
                                   float* __restrict__ scale, float* __restrict__ shift, float invM)
{
    int c = threadIdx.x;
    float mu = sum[c] * invM;
    float var = sumsq[c] * invM - mu * mu;
    float sc = gamma[c] * rsqrtf(var + BN_EPS);
    scale[c] = sc;
    shift[c] = beta[c] - mu * sc;
}

__global__ void bn_apply_kernel(float* __restrict__ X,
                                const float* __restrict__ scale, const float* __restrict__ shift)
{
    int i = blockIdx.x * blockDim.x + threadIdx.x;
    if (i < NN * DD) {
        int c = i & (DD - 1);
        X[i] = X[i] * scale[c] + shift[c];
    }
}

// ---------------- launch ----------------------------------------------------
extern "C" void kernel_launch(void* const* d_in, const int* in_sizes, int n_in,
                              void* d_out, int out_size)
{
    const float* x         = (const float*)d_in[0];
    const int*   src       = (const int*)  d_in[1];
    const int*   dst       = (const int*)  d_in[2];
    const float* W         = (const float*)d_in[3];
    const float* attn_l    = (const float*)d_in[4];
    const float* attn_r    = (const float*)d_in[5];
    // d_in[6]  bias_gat : absorbed by BN1
    const float* bn1_gamma = (const float*)d_in[7];
    const float* bn1_beta  = (const float*)d_in[8];
    const float* W1        = (const float*)d_in[9];
    const float* b1        = (const float*)d_in[10];
    const float* W2        = (const float*)d_in[11];
    // d_in[12] b2       : absorbed by BN2
    const float* bn2_gamma = (const float*)d_in[13];
    const float* bn2_beta  = (const float*)d_in[14];
    float* out = (float*)d_out;

    float *p_feat, *p_el, *p_er, *p_agg, *p_mid, *p_stats;
    float *p_scale1, *p_shift1, *p_scale2, *p_shift2;
    int *p_deg, *p_off, *p_cursor, *p_csr;
    cudaGetSymbolAddress((void**)&p_feat,   g_feat);
    cudaGetSymbolAddress((void**)&p_el,     g_el);
    cudaGetSymbolAddress((void**)&p_er,     g_er);
    cudaGetSymbolAddress((void**)&p_agg,    g_agg);
    cudaGetSymbolAddress((void**)&p_mid,    g_mid);
    cudaGetSymbolAddress((void**)&p_stats,  g_stats);
    cudaGetSymbolAddress((void**)&p_scale1, g_scale1);
    cudaGetSymbolAddress((void**)&p_shift1, g_shift1);
    cudaGetSymbolAddress((void**)&p_scale2, g_scale2);
    cudaGetSymbolAddress((void**)&p_shift2, g_shift2);
    cudaGetSymbolAddress((void**)&p_deg,    g_deg);
    cudaGetSymbolAddress((void**)&p_off,    g_off);
    cudaGetSymbolAddress((void**)&p_cursor, g_cursor);
    cudaGetSymbolAddress((void**)&p_csr,    g_csr_src);

    // ---- CSR build (independent of GEMM1) ----
    zero_i_kernel<<<(NN + 255) / 256, 256>>>(p_deg, NN);
    hist_kernel<<<(EE + 255) / 256, 256>>>(dst, p_deg);
    scan_kernel<<<1, SCAN_T>>>(p_deg, p_off, p_cursor);
    scatter_kernel<<<(EE + 255) / 256, 256>>>(src, dst, p_cursor, p_csr);

    zero_f_kernel<<<(4 * DD + 255) / 256, 256>>>(p_stats, 4 * DD);

    // ---- feat = x @ W ----
    sgemm128<false, false><<<dim3(DD / 128, (NN + 127) / 128), 256>>>(
        x, W, p_feat, NN, DD, DD, nullptr, nullptr, nullptr);

    // ---- attention logits ----
    eler_kernel<<<(NN * 32 + 255) / 256, 256>>>(p_feat, attn_l, attn_r, p_el, p_er);

    // ---- gather aggregation: normalized GAT output, no fp atomics ----
    agg_kernel<<<(NN * 32 + 255) / 256, 256>>>(p_off, p_csr, p_el, p_er,
                                               p_feat, p_agg);

    // ---- BN1 stats (bias_gat absorbed); apply fused into GEMM2 A-load ----
    col_stats_kernel<<<1024, 128>>>(p_agg, NN, p_stats, p_stats + DD);
    bn_finalize_kernel<<<1, DD>>>(p_stats, p_stats + DD, bn1_gamma, bn1_beta,
                                  p_scale1, p_shift1, 1.0f / NN);

    // ---- mid = relu(BN1(agg) @ W1 + b1) ----
    sgemm128<true, true><<<dim3(HIDDEN / 128, (NN + 127) / 128), 256>>>(
        p_agg, W1, p_mid, NN, HIDDEN, DD, p_scale1, p_shift1, b1);

    // ---- out_pre = mid @ W2 (b2 absorbed by BN2) ----
    sgemm128<false, false><<<dim3(DD / 128, (NN + 127) / 128), 256>>>(
        p_mid, W2, out, NN, DD, HIDDEN, nullptr, nullptr, nullptr);

    // ---- BN2 stats + in-place apply ----
    col_stats_kernel<<<1024, 128>>>(out, NN, p_stats + 2 * DD, p_stats + 3 * DD);
    bn_finalize_kernel<<<1, DD>>>(p_stats + 2 * DD, p_stats + 3 * DD, bn2_gamma,
                                  bn2_beta, p_scale2, p_shift2, 1.0f / NN);
    bn_apply_kernel<<<(NN * DD + 255) / 256, 256>>>(out, p_scale2, p_shift2);
}

// round 8
// speedup vs baseline: 1.2829x; 1.0086x over previous
#include <cuda_runtime.h>
#include <math.h>
#include <stdint.h>

#define NN 50000
#define EE 800000
#define DD 128
#define HH 8
#define HIDDEN 512
#define BN_EPS 1e-5f
#define SLOPE 0.2f

// ---------------- scratch (static __device__ arrays; no allocation) ----------
__device__ float g_feat[(size_t)NN * DD];            // x @ W            25.6 MB
__device__ float g_el[NN * HH];
__device__ float g_er[NN * HH];
__device__ float g_agg[(size_t)NN * DD];             // normalized GAT output
__device__ float g_mid[(size_t)NN * HIDDEN];         // hidden activations 102 MB
__device__ float g_stats[4 * DD];
__device__ float g_scale1[DD], g_shift1[DD];
__device__ float g_scale2[DD], g_shift2[DD];
// CSR of incoming edges per dst node
__device__ int g_deg[NN];
__device__ int g_off[NN + 1];
__device__ int g_cursor[NN];
__device__ int g_csr_src[EE];

// ---------------- packed f32x2 helpers ---------------------------------------
typedef unsigned long long ull;

__device__ __forceinline__ void ffma2(ull& d, ull a, ull b) {
    asm("fma.rn.f32x2 %0, %1, %2, %0;" : "+l"(d) : "l"(a), "l"(b));
}
__device__ __forceinline__ ull pack2(float v) {
    ull r;
    asm("mov.b64 %0, {%1, %1};" : "=l"(r) : "r"(__float_as_uint(v)));
    return r;
}

// ---------------- utility ---------------------------------------------------
__global__ void zero_f_kernel(float* __restrict__ p, int n) {
    int i = blockIdx.x * blockDim.x + threadIdx.x;
    if (i < n) p[i] = 0.0f;
}
__global__ void zero_i_kernel(int* __restrict__ p, int n) {
    int i = blockIdx.x * blockDim.x + threadIdx.x;
    if (i < n) p[i] = 0;
}

// ---------------- CSR build --------------------------------------------------
__global__ void hist_kernel(const int* __restrict__ dst, int* __restrict__ deg) {
    int e = blockIdx.x * blockDim.x + threadIdx.x;
    if (e < EE) atomicAdd(&deg[dst[e]], 1);
}

#define SCAN_T 1024
#define SCAN_PER 49
__global__ void __launch_bounds__(SCAN_T)
scan_kernel(const int* __restrict__ deg, int* __restrict__ off, int* __restrict__ cursor) {
    __shared__ int part[SCAN_T];
    int t = threadIdx.x;
    int base = t * SCAN_PER;
    int s = 0;
#pragma unroll
    for (int i = 0; i < SCAN_PER; i++) {
        int idx = base + i;
        if (idx < NN) s += deg[idx];
    }
    part[t] = s;
    __syncthreads();
    for (int d = 1; d < SCAN_T; d <<= 1) {
        int add = (t >= d) ? part[t - d] : 0;
        __syncthreads();
        part[t] += add;
        __syncthreads();
    }
    int running = part[t] - s;
#pragma unroll
    for (int i = 0; i < SCAN_PER; i++) {
        int idx = base + i;
        if (idx < NN) {
            off[idx] = running;
            cursor[idx] = running;
            running += deg[idx];
        }
    }
    if (t == SCAN_T - 1) off[NN] = running;
}

__global__ void scatter_kernel(const int* __restrict__ src, const int* __restrict__ dst,
                               int* __restrict__ cursor, int* __restrict__ csr) {
    int e = blockIdx.x * blockDim.x + threadIdx.x;
    if (e >= EE) return;
    int pos = atomicAdd(&cursor[dst[e]], 1);
    csr[pos] = src[e];
}

// ---------------- SGEMM (packed f32x2): C[M,N] = op(A[M,K] @ B[K,N]) --------
// BM=128, BN=128, BK=16, 256 threads, 8x8 per thread. Accumulators are 64-bit
// column pairs driven by fma.rn.f32x2 (Blackwell packed fp32 FMA, 2 FMA/instr).
template <bool ASCALE, bool BIASR>
__global__ void __launch_bounds__(256, 2)
sgemm128(const float* __restrict__ A, const float* __restrict__ B,
         float* __restrict__ C, int M, int N, int K,
         const float* __restrict__ ascale, const float* __restrict__ ashift,
         const float* __restrict__ bias)
{
    __shared__ float As[16][128];      // transposed: As[k][m]
    __shared__ float Bs[16][128];      // Bs[k][n]

    const int tid = threadIdx.x;
    const int bm = blockIdx.y * 128;
    const int bn = blockIdx.x * 128;
    const int tx = tid & 15;
    const int ty = tid >> 4;

    int ar[2], ac[2], br[2], bc[2];
#pragma unroll
    for (int j = 0; j < 2; j++) {
        int idx = tid * 2 + j;
        ar[j] = idx >> 2;
        ac[j] = (idx & 3) * 4;
        br[j] = idx >> 5;
        bc[j] = (idx & 31) * 4;
    }

    float4 pa[2], pb[2];

    auto loadA = [&](int k0) {
#pragma unroll
        for (int j = 0; j < 2; j++) {
            int grow = bm + ar[j];
            float4 v = make_float4(0.f, 0.f, 0.f, 0.f);
            if (grow < M)
                v = *(const float4*)(A + (size_t)grow * K + k0 + ac[j]);
            if (ASCALE) {
                int kc = k0 + ac[j];
                v.x = fmaf(v.x, ascale[kc + 0], ashift[kc + 0]);
                v.y = fmaf(v.y, ascale[kc + 1], ashift[kc + 1]);
                v.z = fmaf(v.z, ascale[kc + 2], ashift[kc + 2]);
                v.w = fmaf(v.w, ascale[kc + 3], ashift[kc + 3]);
            }
            pa[j] = v;
        }
    };
    auto loadB = [&](int k0) {
#pragma unroll
        for (int j = 0; j < 2; j++)
            pb[j] = *(const float4*)(B + (size_t)(k0 + br[j]) * N + bn + bc[j]);
    };

    // acc2[i][j]: row i (of 8), column pair j: j=0 -> cols (tx*4+0, tx*4+1),
    // j=1 -> (+2,+3), j=2 -> (64+tx*4+0, +1), j=3 -> (64+tx*4+2, +3)
    ull acc2[8][4];
#pragma unroll
    for (int i = 0; i < 8; i++)
#pragma unroll
        for (int j = 0; j < 4; j++) acc2[i][j] = 0ull;

    loadA(0);
    loadB(0);

    for (int k0 = 0; k0 < K; k0 += 16) {
#pragma unroll
        for (int j = 0; j < 2; j++) {
            As[ac[j] + 0][ar[j]] = pa[j].x;
            As[ac[j] + 1][ar[j]] = pa[j].y;
            As[ac[j] + 2][ar[j]] = pa[j].z;
            As[ac[j] + 3][ar[j]] = pa[j].w;
            *(float4*)&Bs[br[j]][bc[j]] = pb[j];
        }
        __syncthreads();

        if (k0 + 16 < K) {
            loadA(k0 + 16);
            loadB(k0 + 16);
        }

#pragma unroll
        for (int kk = 0; kk < 16; kk++) {
            float4 a0 = *(const float4*)&As[kk][ty * 4];
            float4 a1 = *(const float4*)&As[kk][64 + ty * 4];
            // B column pairs: direct 64-bit loads from shared
            ull bp[4];
            bp[0] = *(const ull*)&Bs[kk][tx * 4 + 0];
            bp[1] = *(const ull*)&Bs[kk][tx * 4 + 2];
            bp[2] = *(const ull*)&Bs[kk][64 + tx * 4 + 0];
            bp[3] = *(const ull*)&Bs[kk][64 + tx * 4 + 2];
            // A replicated into both packed halves
            ull ap[8];
            ap[0] = pack2(a0.x); ap[1] = pack2(a0.y);
            ap[2] = pack2(a0.z); ap[3] = pack2(a0.w);
            ap[4] = pack2(a1.x); ap[5] = pack2(a1.y);
            ap[6] = pack2(a1.z); ap[7] = pack2(a1.w);
#pragma unroll
            for (int i = 0; i < 8; i++)
#pragma unroll
                for (int j = 0; j < 4; j++)
                    ffma2(acc2[i][j], ap[i], bp[j]);
        }
        __syncthreads();
    }

    // ---- epilogue ----
    union PU { ull u; float2 f; };
#pragma unroll
    for (int ri = 0; ri < 8; ri++) {
        int lr = (ri < 4) ? (ty * 4 + ri) : (64 + ty * 4 + (ri - 4));
        int gr = bm + lr;
        if (gr >= M) continue;
#pragma unroll
        for (int cf = 0; cf < 2; cf++) {
            int gc = bn + cf * 64 + tx * 4;
            PU p0, p1;
            p0.u = acc2[ri][cf * 2 + 0];
            p1.u = acc2[ri][cf * 2 + 1];
            float4 o = make_float4(p0.f.x, p0.f.y, p1.f.x, p1.f.y);
            if (BIASR) {
                o.x = fmaxf(o.x + bias[gc + 0], 0.0f);
                o.y = fmaxf(o.y + bias[gc + 1], 0.0f);
                o.z = fmaxf(o.z + bias[gc + 2], 0.0f);
                o.w = fmaxf(o.w + bias[gc + 3], 0.0f);
            }
            *(float4*)(C + (size_t)gr * N + gc) = o;
        }
    }
}

// ---------------- per-node attention logits (el, er) ------------------------
__global__ void eler_kernel(const float* __restrict__ feat,
                            const float* __restrict__ attn_l,
                            const float* __restrict__ attn_r,
                            float* __restrict__ el, float* __restrict__ er)
{
    int n = (blockIdx.x * blockDim.x + threadIdx.x) >> 5;
    int lane = threadIdx.x & 31;
    if (n >= NN) return;
    float4 v  = ((const float4*)(feat + (size_t)n * DD))[lane];
    float4 al = ((const float4*)attn_l)[lane];
    float4 ar = ((const float4*)attn_r)[lane];
    float pl = v.x * al.x + v.y * al.y + v.z * al.z + v.w * al.w;
    float pr = v.x * ar.x + v.y * ar.y + v.z * ar.z + v.w * ar.w;
    pl += __shfl_xor_sync(0xFFFFFFFFu, pl, 1);
    pl += __shfl_xor_sync(0xFFFFFFFFu, pl, 2);
    pr += __shfl_xor_sync(0xFFFFFFFFu, pr, 1);
    pr += __shfl_xor_sync(0xFFFFFFFFu, pr, 2);
    if ((lane & 3) == 0) {
        int h = lane >> 2;
        el[n * HH + h] = pl;
        er[n * HH + h] = pr;
    }
}

// ---------------- warp-per-dst gather aggregation (no fp atomics) ------------
__global__ void agg_kernel(const int* __restrict__ off, const int* __restrict__ csr,
                           const float* __restrict__ el, const float* __restrict__ er,
                           const float* __restrict__ feat, float* __restrict__ agg)
{
    int d = (blockIdx.x * blockDim.x + threadIdx.x) >> 5;
    int lane = threadIdx.x & 31;
    if (d >= NN) return;
    int h = lane >> 2;
    float erv = er[d * HH + h];
    int i0 = off[d], i1 = off[d + 1];
    float4 acc = make_float4(0.f, 0.f, 0.f, 0.f);
    float wsum = 0.0f;
    for (int i = i0; i < i1; i++) {
        int s = __ldg(&csr[i]);
        float x = el[s * HH + h] + erv;
        x = (x > 0.0f) ? x : SLOPE * x;
        float w = __expf(x);
        wsum += w;
        float4 v = ((const float4*)(feat + (size_t)s * DD))[lane];
        acc.x = fmaf(w, v.x, acc.x);
        acc.y = fmaf(w, v.y, acc.y);
        acc.z = fmaf(w, v.z, acc.z);
        acc.w = fmaf(w, v.w, acc.w);
    }
    float4 o = make_float4(0.f, 0.f, 0.f, 0.f);
    if (i1 > i0) {
        float inv = 1.0f / wsum;
        o.x = acc.x * inv; o.y = acc.y * inv;
        o.z = acc.z * inv; o.w = acc.w * inv;
    }
    ((float4*)(agg + (size_t)d * DD))[lane] = o;
}

// ---------------- column statistics ------------------------------------------
__global__ void col_stats_kernel(const float* __restrict__ X, int M,
                                 float* __restrict__ sum, float* __restrict__ sumsq)
{
    int c = threadIdx.x;
    float s = 0.0f, s2 = 0.0f;
    for (int r = blockIdx.x; r < M; r += gridDim.x) {
        float v = X[(size_t)r * DD + c];
        s += v;
        s2 += v * v;
    }
    atomicAdd(&sum[c], s);
    atomicAdd(&sumsq[c], s2);
}

__global__ void bn_finalize_kernel(const float* __restrict__ sum, const float* __restrict__ sumsq,
                                   const float* __restrict__ gamma, const float* __restrict__ beta,
                                   float* __restrict__ scale, float* __restrict__ shift, float invM)
{
    int c = threadIdx.x;
    float mu = sum[c] * invM;
    float var = sumsq[c] * invM - mu * mu;
    float sc = gamma[c] * rsqrtf(var + BN_EPS);
    scale[c] = sc;
    shift[c] = beta[c] - mu * sc;
}

__global__ void bn_apply_kernel(float* __restrict__ X,
                                const float* __restrict__ scale, const float* __restrict__ shift)
{
    int i = blockIdx.x * blockDim.x + threadIdx.x;
    if (i < NN * DD) {
        int c = i & (DD - 1);
        X[i] = X[i] * scale[c] + shift[c];
    }
}

// ---------------- launch ----------------------------------------------------
extern "C" void kernel_launch(void* const* d_in, const int* in_sizes, int n_in,
                              void* d_out, int out_size)
{
    const float* x         = (const float*)d_in[0];
    const int*   src       = (const int*)  d_in[1];
    const int*   dst       = (const int*)  d_in[2];
    const float* W         = (const float*)d_in[3];
    const float* attn_l    = (const float*)d_in[4];
    const float* attn_r    = (const float*)d_in[5];
    // d_in[6]  bias_gat : absorbed by BN1
    const float* bn1_gamma = (const float*)d_in[7];
    const float* bn1_beta  = (const float*)d_in[8];
    const float* W1        = (const float*)d_in[9];
    const float* b1        = (const float*)d_in[10];
    const float* W2        = (const float*)d_in[11];
    // d_in[12] b2       : absorbed by BN2
    const float* bn2_gamma = (const float*)d_in[13];
    const float* bn2_beta  = (const float*)d_in[14];
    float* out = (float*)d_out;

    float *p_feat, *p_el, *p_er, *p_agg, *p_mid, *p_stats;
    float *p_scale1, *p_shift1, *p_scale2, *p_shift2;
    int *p_deg, *p_off, *p_cursor, *p_csr;
    cudaGetSymbolAddress((void**)&p_feat,   g_feat);
    cudaGetSymbolAddress((void**)&p_el,     g_el);
    cudaGetSymbolAddress((void**)&p_er,     g_er);
    cudaGetSymbolAddress((void**)&p_agg,    g_agg);
    cudaGetSymbolAddress((void**)&p_mid,    g_mid);
    cudaGetSymbolAddress((void**)&p_stats,  g_stats);
    cudaGetSymbolAddress((void**)&p_scale1, g_scale1);
    cudaGetSymbolAddress((void**)&p_shift1, g_shift1);
    cudaGetSymbolAddress((void**)&p_scale2, g_scale2);
    cudaGetSymbolAddress((void**)&p_shift2, g_shift2);
    cudaGetSymbolAddress((void**)&p_deg,    g_deg);
    cudaGetSymbolAddress((void**)&p_off,    g_off);
    cudaGetSymbolAddress((void**)&p_cursor, g_cursor);
    cudaGetSymbolAddress((void**)&p_csr,    g_csr_src);

    // ---- CSR build ----
    zero_i_kernel<<<(NN + 255) / 256, 256>>>(p_deg, NN);
    hist_kernel<<<(EE + 255) / 256, 256>>>(dst, p_deg);
    scan_kernel<<<1, SCAN_T>>>(p_deg, p_off, p_cursor);
    scatter_kernel<<<(EE + 255) / 256, 256>>>(src, dst, p_cursor, p_csr);

    zero_f_kernel<<<(4 * DD + 255) / 256, 256>>>(p_stats, 4 * DD);

    // ---- feat = x @ W ----
    sgemm128<false, false><<<dim3(DD / 128, (NN + 127) / 128), 256>>>(
        x, W, p_feat, NN, DD, DD, nullptr, nullptr, nullptr);

    // ---- attention logits ----
    eler_kernel<<<(NN * 32 + 255) / 256, 256>>>(p_feat, attn_l, attn_r, p_el, p_er);

    // ---- gather aggregation ----
    agg_kernel<<<(NN * 32 + 255) / 256, 256>>>(p_off, p_csr, p_el, p_er,
                                               p_feat, p_agg);

    // ---- BN1 stats; apply fused into GEMM2 A-load ----
    col_stats_kernel<<<1024, 128>>>(p_agg, NN, p_stats, p_stats + DD);
    bn_finalize_kernel<<<1, DD>>>(p_stats, p_stats + DD, bn1_gamma, bn1_beta,
                                  p_scale1, p_shift1, 1.0f / NN);

    // ---- mid = relu(BN1(agg) @ W1 + b1) ----
    sgemm128<true, true><<<dim3(HIDDEN / 128, (NN + 127) / 128), 256>>>(
        p_agg, W1, p_mid, NN, HIDDEN, DD, p_scale1, p_shift1, b1);

    // ---- out_pre = mid @ W2 (b2 absorbed by BN2) ----
    sgemm128<false, false><<<dim3(DD / 128, (NN + 127) / 128), 256>>>(
        p_mid, W2, out, NN, DD, HIDDEN, nullptr, nullptr, nullptr);

    // ---- BN2 stats + in-place apply ----
    col_stats_kernel<<<1024, 128>>>(out, NN, p_stats + 2 * DD, p_stats + 3 * DD);
    bn_finalize_kernel<<<1, DD>>>(p_stats + 2 * DD, p_stats + 3 * DD, bn2_gamma,
                                  bn2_beta, p_scale2, p_shift2, 1.0f / NN);
    bn_apply_kernel<<<(NN * DD + 255) / 256, 256>>>(out, p_scale2, p_shift2);
}

// round 10
// speedup vs baseline: 1.4814x; 1.1547x over previous
#include <cuda_runtime.h>
#include <cuda_bf16.h>
#include <math.h>
#include <stdint.h>

#define NN 50000
#define EE 800000
#define DD 128
#define HH 8
#define HIDDEN 512
#define BN_EPS 1e-5f
#define SLOPE 0.2f

// ---------------- scratch (static __device__ arrays; no allocation) ----------
__device__ float g_feat[(size_t)NN * DD];
__device__ float g_el[NN * HH];
__device__ float g_er[NN * HH];
__device__ float g_agg[(size_t)NN * DD];
__device__ float g_mid[(size_t)NN * HIDDEN];
__device__ float g_stats[4 * DD];
__device__ float g_scale1[DD], g_shift1[DD];
__device__ float g_scale2[DD], g_shift2[DD];
// CSR of incoming edges per dst node
__device__ int g_deg[NN];
__device__ int g_off[NN + 1];
__device__ int g_cursor[NN];
__device__ int g_csr_src[EE];
// transposed + bf16-split weights: [N,K] K-major
__device__ __nv_bfloat16 g_wT_hi[DD * DD],      g_wT_lo[DD * DD];
__device__ __nv_bfloat16 g_w1T_hi[HIDDEN * DD], g_w1T_lo[HIDDEN * DD];
__device__ __nv_bfloat16 g_w2T_hi[DD * HIDDEN], g_w2T_lo[DD * HIDDEN];

// ---------------- bf16 helpers ------------------------------------------------
__device__ __forceinline__ void split_pack(float v0, float v1,
                                           uint32_t& hi, uint32_t& lo) {
    __nv_bfloat16 h0 = __float2bfloat16_rn(v0);
    __nv_bfloat16 h1 = __float2bfloat16_rn(v1);
    float l0 = v0 - __bfloat162float(h0);
    float l1 = v1 - __bfloat162float(h1);
    __nv_bfloat16 g0 = __float2bfloat16_rn(l0);
    __nv_bfloat16 g1 = __float2bfloat16_rn(l1);
    hi = ((uint32_t)__bfloat16_as_ushort(h1) << 16) | __bfloat16_as_ushort(h0);
    lo = ((uint32_t)__bfloat16_as_ushort(g1) << 16) | __bfloat16_as_ushort(g0);
}

__device__ __forceinline__ void mma16(float* d, const uint32_t* a, const uint32_t* b) {
    asm volatile(
        "mma.sync.aligned.m16n8k16.row.col.f32.bf16.bf16.f32 "
        "{%0,%1,%2,%3}, {%4,%5,%6,%7}, {%8,%9}, {%0,%1,%2,%3};"
        : "+f"(d[0]), "+f"(d[1]), "+f"(d[2]), "+f"(d[3])
        : "r"(a[0]), "r"(a[1]), "r"(a[2]), "r"(a[3]), "r"(b[0]), "r"(b[1]));
}

// ---------------- utility ---------------------------------------------------
__global__ void zero_f_kernel(float* __restrict__ p, int n) {
    int i = blockIdx.x * blockDim.x + threadIdx.x;
    if (i < n) p[i] = 0.0f;
}
__global__ void zero_i_kernel(int* __restrict__ p, int n) {
    int i = blockIdx.x * blockDim.x + threadIdx.x;
    if (i < n) p[i] = 0;
}

// transpose B[K,N] -> Bt[N,K] split into bf16 hi/lo
__global__ void prep_b_kernel(const float* __restrict__ B,
                              __nv_bfloat16* __restrict__ th,
                              __nv_bfloat16* __restrict__ tl, int K, int N) {
    int i = blockIdx.x * blockDim.x + threadIdx.x;
    if (i >= N * K) return;
    int n = i / K, k = i - n * K;
    float v = B[(size_t)k * N + n];
    __nv_bfloat16 h = __float2bfloat16_rn(v);
    th[i] = h;
    tl[i] = __float2bfloat16_rn(v - __bfloat162float(h));
}

// ---------------- CSR build --------------------------------------------------
__global__ void hist_kernel(const int* __restrict__ dst, int* __restrict__ deg) {
    int e = blockIdx.x * blockDim.x + threadIdx.x;
    if (e < EE) atomicAdd(&deg[dst[e]], 1);
}

#define SCAN_T 1024
#define SCAN_PER 49
__global__ void __launch_bounds__(SCAN_T)
scan_kernel(const int* __restrict__ deg, int* __restrict__ off, int* __restrict__ cursor) {
    __shared__ int part[SCAN_T];
    int t = threadIdx.x;
    int base = t * SCAN_PER;
    int s = 0;
#pragma unroll
    for (int i = 0; i < SCAN_PER; i++) {
        int idx = base + i;
        if (idx < NN) s += deg[idx];
    }
    part[t] = s;
    __syncthreads();
    for (int d = 1; d < SCAN_T; d <<= 1) {
        int add = (t >= d) ? part[t - d] : 0;
        __syncthreads();
        part[t] += add;
        __syncthreads();
    }
    int running = part[t] - s;
#pragma unroll
    for (int i = 0; i < SCAN_PER; i++) {
        int idx = base + i;
        if (idx < NN) {
            off[idx] = running;
            cursor[idx] = running;
            running += deg[idx];
        }
    }
    if (t == SCAN_T - 1) off[NN] = running;
}

__global__ void scatter_kernel(const int* __restrict__ src, const int* __restrict__ dst,
                               int* __restrict__ cursor, int* __restrict__ csr) {
    int e = blockIdx.x * blockDim.x + threadIdx.x;
    if (e >= EE) return;
    int pos = atomicAdd(&cursor[dst[e]], 1);
    csr[pos] = src[e];
}

// ---------------- 3x bf16-split mma GEMM: C[M,N] = A[M,K] @ Bt[N,K]^T --------
// CTA 128x128, BK=64, 8 warps (2x4), warp tile 64x32, m16n8k16.
// SMEM rows = 72 bf16 = 36 words; frag-load bank = (4*row + tig) mod 32, all
// distinct within a warp -> conflict-free LDS.32.
// ASCALE: BN fold on A columns. BIASR: relu(C + bias[n]).
#define AROW32 36
#define SMEM_BF (4 * 128 * AROW32 * 4)   // 73728 bytes

template <bool ASCALE, bool BIASR>
__global__ void __launch_bounds__(256)
sgemm_bf(const float* __restrict__ A, const __nv_bfloat16* __restrict__ Bth,
         const __nv_bfloat16* __restrict__ Btl, float* __restrict__ C,
         int M, int N, int K,
         const float* __restrict__ ascale, const float* __restrict__ ashift,
         const float* __restrict__ bias)
{
    extern __shared__ uint32_t sm32[];
    uint32_t* Ah = sm32;                 // [128][36] words (bf16x2)
    uint32_t* Al = Ah + 128 * AROW32;
    uint32_t* Bh = Al + 128 * AROW32;
    uint32_t* Bl = Bh + 128 * AROW32;

    const int tid = threadIdx.x;
    const int wid = tid >> 5, lane = tid & 31;
    const int gid = lane >> 2, tig = lane & 3;
    const int bm = blockIdx.y * 128, bn = blockIdx.x * 128;
    const int wm = (wid >> 2) * 64;
    const int wn = (wid & 3) * 32;

    float acc[4][4][4];
#pragma unroll
    for (int i = 0; i < 4; i++)
#pragma unroll
        for (int j = 0; j < 4; j++)
#pragma unroll
            for (int r = 0; r < 4; r++) acc[i][j][r] = 0.0f;

    for (int k0 = 0; k0 < K; k0 += 64) {
        // ---- A fill: 128x64 fp32 -> bf16 hi/lo split (+ optional BN fold) ----
#pragma unroll
        for (int j = 0; j < 8; j++) {
            int task = tid + j * 256;        // 0..2047
            int r = task >> 4, kq = (task & 15) * 4;
            int gr = bm + r;
            float4 v = make_float4(0.f, 0.f, 0.f, 0.f);
            if (gr < M) v = *(const float4*)(A + (size_t)gr * K + k0 + kq);
            if (ASCALE) {
                int kc = k0 + kq;
                v.x = fmaf(v.x, ascale[kc + 0], ashift[kc + 0]);
                v.y = fmaf(v.y, ascale[kc + 1], ashift[kc + 1]);
                v.z = fmaf(v.z, ascale[kc + 2], ashift[kc + 2]);
                v.w = fmaf(v.w, ascale[kc + 3], ashift[kc + 3]);
            }
            uint32_t h01, l01, h23, l23;
            split_pack(v.x, v.y, h01, l01);
            split_pack(v.z, v.w, h23, l23);
            int o = r * AROW32 + (kq >> 1);
            Ah[o] = h01; Ah[o + 1] = h23;
            Al[o] = l01; Al[o + 1] = l23;
        }
        // ---- B fill: pre-split bf16, straight uint4 copies ----
#pragma unroll
        for (int j = 0; j < 4; j++) {
            int task = tid + j * 256;        // 0..1023
            int r = task >> 3, kq = (task & 7) * 8;
            const uint16_t* ph = (const uint16_t*)Bth + (size_t)(bn + r) * K + k0 + kq;
            const uint16_t* pl = (const uint16_t*)Btl + (size_t)(bn + r) * K + k0 + kq;
            uint4 h = *(const uint4*)ph;
            uint4 l = *(const uint4*)pl;
            int o = r * AROW32 + (kq >> 1);
            *(uint4*)&Bh[o] = h;
            *(uint4*)&Bl[o] = l;
        }
        __syncthreads();

        // ---- compute: 4 k-steps of 16 ----
#pragma unroll
        for (int ks = 0; ks < 4; ks++) {
            int kw = ks * 8;                 // word offset of this 16-k step
            uint32_t bh[4][2], bl[4][2];
#pragma unroll
            for (int nt = 0; nt < 4; nt++) {
                int base = (wn + nt * 8 + gid) * AROW32 + kw + tig;
                bh[nt][0] = Bh[base];  bh[nt][1] = Bh[base + 4];
                bl[nt][0] = Bl[base];  bl[nt][1] = Bl[base + 4];
            }
#pragma unroll
            for (int mt = 0; mt < 4; mt++) {
                int base = (wm + mt * 16 + gid) * AROW32 + kw + tig;
                uint32_t ah[4], al[4];
                ah[0] = Ah[base];
                ah[1] = Ah[base + 8 * AROW32];
                ah[2] = Ah[base + 4];
                ah[3] = Ah[base + 8 * AROW32 + 4];
                al[0] = Al[base];
                al[1] = Al[base + 8 * AROW32];
                al[2] = Al[base + 4];
                al[3] = Al[base + 8 * AROW32 + 4];
#pragma unroll
                for (int nt = 0; nt < 4; nt++) {
                    mma16(acc[mt][nt], ah, bh[nt]);   // hi*hi
                    mma16(acc[mt][nt], ah, bl[nt]);   // hi*lo
                    mma16(acc[mt][nt], al, bh[nt]);   // lo*hi
                }
            }
        }
        __syncthreads();
    }

    // ---- epilogue: register -> global (float2), fused bias+relu ----
#pragma unroll
    for (int mt = 0; mt < 4; mt++) {
        int r0 = bm + wm + mt * 16 + gid;
#pragma unroll
        for (int nt = 0; nt < 4; nt++) {
            int c0 = bn + wn + nt * 8 + tig * 2;
            float2 v0 = make_float2(acc[mt][nt][0], acc[mt][nt][1]);
            float2 v1 = make_float2(acc[mt][nt][2], acc[mt][nt][3]);
            if (BIASR) {
                float b0 = bias[c0], b1 = bias[c0 + 1];
                v0.x = fmaxf(v0.x + b0, 0.f); v0.y = fmaxf(v0.y + b1, 0.f);
                v1.x = fmaxf(v1.x + b0, 0.f); v1.y = fmaxf(v1.y + b1, 0.f);
            }
            if (r0 < M)     *(float2*)(C + (size_t)r0 * N + c0) = v0;
            if (r0 + 8 < M) *(float2*)(C + (size_t)(r0 + 8) * N + c0) = v1;
        }
    }
}

// ---------------- per-node attention logits (el, er) ------------------------
__global__ void eler_kernel(const float* __restrict__ feat,
                            const float* __restrict__ attn_l,
                            const float* __restrict__ attn_r,
                            float* __restrict__ el, float* __restrict__ er)
{
    int n = (blockIdx.x * blockDim.x + threadIdx.x) >> 5;
    int lane = threadIdx.x & 31;
    if (n >= NN) return;
    float4 v  = ((const float4*)(feat + (size_t)n * DD))[lane];
    float4 al = ((const float4*)attn_l)[lane];
    float4 ar = ((const float4*)attn_r)[lane];
    float pl = v.x * al.x + v.y * al.y + v.z * al.z + v.w * al.w;
    float pr = v.x * ar.x + v.y * ar.y + v.z * ar.z + v.w * ar.w;
    pl += __shfl_xor_sync(0xFFFFFFFFu, pl, 1);
    pl += __shfl_xor_sync(0xFFFFFFFFu, pl, 2);
    pr += __shfl_xor_sync(0xFFFFFFFFu, pr, 1);
    pr += __shfl_xor_sync(0xFFFFFFFFu, pr, 2);
    if ((lane & 3) == 0) {
        int h = lane >> 2;
        el[n * HH + h] = pl;
        er[n * HH + h] = pr;
    }
}

// ---------------- warp-per-dst gather aggregation (no fp atomics) ------------
__global__ void agg_kernel(const int* __restrict__ off, const int* __restrict__ csr,
                           const float* __restrict__ el, const float* __restrict__ er,
                           const float* __restrict__ feat, float* __restrict__ agg)
{
    int d = (blockIdx.x * blockDim.x + threadIdx.x) >> 5;
    int lane = threadIdx.x & 31;
    if (d >= NN) return;
    int h = lane >> 2;
    float erv = er[d * HH + h];
    int i0 = off[d], i1 = off[d + 1];
    float4 acc = make_float4(0.f, 0.f, 0.f, 0.f);
    float wsum = 0.0f;
    for (int i = i0; i < i1; i++) {
        int s = __ldg(&csr[i]);
        float x = el[s * HH + h] + erv;
        x = (x > 0.0f) ? x : SLOPE * x;
        float w = __expf(x);
        wsum += w;
        float4 v = ((const float4*)(feat + (size_t)s * DD))[lane];
        acc.x = fmaf(w, v.x, acc.x);
        acc.y = fmaf(w, v.y, acc.y);
        acc.z = fmaf(w, v.z, acc.z);
        acc.w = fmaf(w, v.w, acc.w);
    }
    float4 o = make_float4(0.f, 0.f, 0.f, 0.f);
    if (i1 > i0) {
        float inv = 1.0f / wsum;
        o.x = acc.x * inv; o.y = acc.y * inv;
        o.z = acc.z * inv; o.w = acc.w * inv;
    }
    ((float4*)(agg + (size_t)d * DD))[lane] = o;
}

// ---------------- column statistics ------------------------------------------
__global__ void col_stats_kernel(const float* __restrict__ X, int M,
                                 float* __restrict__ sum, float* __restrict__ sumsq)
{
    int c = threadIdx.x;
    float s = 0.0f, s2 = 0.0f;
    for (int r = blockIdx.x; r < M; r += gridDim.x) {
        float v = X[(size_t)r * DD + c];
        s += v;
        s2 += v * v;
    }
    atomicAdd(&sum[c], s);
    atomicAdd(&sumsq[c], s2);
}

__global__ void bn_finalize_kernel(const float* __restrict__ sum, const float* __restrict__ sumsq,
                                   const float* __restrict__ gamma, const float* __restrict__ beta,
                                   float* __restrict__ scale, float* __restrict__ shift, float invM)
{
    int c = threadIdx.x;
    float mu = sum[c] * invM;
    float var = sumsq[c] * invM - mu * mu;
    float sc = gamma[c] * rsqrtf(var + BN_EPS);
    scale[c] = sc;
    shift[c] = beta[c] - mu * sc;
}

__global__ void bn_apply_kernel(float* __restrict__ X,
                                const float* __restrict__ scale, const float* __restrict__ shift)
{
    int i = blockIdx.x * blockDim.x + threadIdx.x;
    if (i < NN * DD) {
        int c = i & (DD - 1);
        X[i] = X[i] * scale[c] + shift[c];
    }
}

// ---------------- launch ----------------------------------------------------
extern "C" void kernel_launch(void* const* d_in, const int* in_sizes, int n_in,
                              void* d_out, int out_size)
{
    const float* x         = (const float*)d_in[0];
    const int*   src       = (const int*)  d_in[1];
    const int*   dst       = (const int*)  d_in[2];
    const float* W         = (const float*)d_in[3];
    const float* attn_l    = (const float*)d_in[4];
    const float* attn_r    = (const float*)d_in[5];
    // d_in[6]  bias_gat : absorbed by BN1
    const float* bn1_gamma = (const float*)d_in[7];
    const float* bn1_beta  = (const float*)d_in[8];
    const float* W1        = (const float*)d_in[9];
    const float* b1        = (const float*)d_in[10];
    const float* W2        = (const float*)d_in[11];
    // d_in[12] b2       : absorbed by BN2
    const float* bn2_gamma = (const float*)d_in[13];
    const float* bn2_beta  = (const float*)d_in[14];
    float* out = (float*)d_out;

    float *p_feat, *p_el, *p_er, *p_agg, *p_mid, *p_stats;
    float *p_scale1, *p_shift1, *p_scale2, *p_shift2;
    int *p_deg, *p_off, *p_cursor, *p_csr;
    __nv_bfloat16 *p_wTh, *p_wTl, *p_w1Th, *p_w1Tl, *p_w2Th, *p_w2Tl;
    cudaGetSymbolAddress((void**)&p_feat,   g_feat);
    cudaGetSymbolAddress((void**)&p_el,     g_el);
    cudaGetSymbolAddress((void**)&p_er,     g_er);
    cudaGetSymbolAddress((void**)&p_agg,    g_agg);
    cudaGetSymbolAddress((void**)&p_mid,    g_mid);
    cudaGetSymbolAddress((void**)&p_stats,  g_stats);
    cudaGetSymbolAddress((void**)&p_scale1, g_scale1);
    cudaGetSymbolAddress((void**)&p_shift1, g_shift1);
    cudaGetSymbolAddress((void**)&p_scale2, g_scale2);
    cudaGetSymbolAddress((void**)&p_shift2, g_shift2);
    cudaGetSymbolAddress((void**)&p_deg,    g_deg);
    cudaGetSymbolAddress((void**)&p_off,    g_off);
    cudaGetSymbolAddress((void**)&p_cursor, g_cursor);
    cudaGetSymbolAddress((void**)&p_csr,    g_csr_src);
    cudaGetSymbolAddress((void**)&p_wTh,  g_wT_hi);
    cudaGetSymbolAddress((void**)&p_wTl,  g_wT_lo);
    cudaGetSymbolAddress((void**)&p_w1Th, g_w1T_hi);
    cudaGetSymbolAddress((void**)&p_w1Tl, g_w1T_lo);
    cudaGetSymbolAddress((void**)&p_w2Th, g_w2T_hi);
    cudaGetSymbolAddress((void**)&p_w2Tl, g_w2T_lo);

    cudaFuncSetAttribute(sgemm_bf<false, false>,
                         cudaFuncAttributeMaxDynamicSharedMemorySize, SMEM_BF);
    cudaFuncSetAttribute(sgemm_bf<true, true>,
                         cudaFuncAttributeMaxDynamicSharedMemorySize, SMEM_BF);

    // ---- weight prep: transpose + bf16 split ----
    prep_b_kernel<<<(DD * DD + 255) / 256, 256>>>(W, p_wTh, p_wTl, DD, DD);
    prep_b_kernel<<<(DD * HIDDEN + 255) / 256, 256>>>(W1, p_w1Th, p_w1Tl, DD, HIDDEN);
    prep_b_kernel<<<(HIDDEN * DD + 255) / 256, 256>>>(W2, p_w2Th, p_w2Tl, HIDDEN, DD);

    // ---- CSR build ----
    zero_i_kernel<<<(NN + 255) / 256, 256>>>(p_deg, NN);
    hist_kernel<<<(EE + 255) / 256, 256>>>(dst, p_deg);
    scan_kernel<<<1, SCAN_T>>>(p_deg, p_off, p_cursor);
    scatter_kernel<<<(EE + 255) / 256, 256>>>(src, dst, p_cursor, p_csr);

    zero_f_kernel<<<(4 * DD + 255) / 256, 256>>>(p_stats, 4 * DD);

    const int MT = (NN + 127) / 128;   // 391

    // ---- feat = x @ W ----
    sgemm_bf<false, false><<<dim3(DD / 128, MT), 256, SMEM_BF>>>(
        x, p_wTh, p_wTl, p_feat, NN, DD, DD, nullptr, nullptr, nullptr);

    // ---- attention logits ----
    eler_kernel<<<(NN * 32 + 255) / 256, 256>>>(p_feat, attn_l, attn_r, p_el, p_er);

    // ---- gather aggregation ----
    agg_kernel<<<(NN * 32 + 255) / 256, 256>>>(p_off, p_csr, p_el, p_er,
                                               p_feat, p_agg);

    // ---- BN1 stats; apply fused into GEMM2 A-load ----
    col_stats_kernel<<<1024, 128>>>(p_agg, NN, p_stats, p_stats + DD);
    bn_finalize_kernel<<<1, DD>>>(p_stats, p_stats + DD, bn1_gamma, bn1_beta,
                                  p_scale1, p_shift1, 1.0f / NN);

    // ---- mid = relu(BN1(agg) @ W1 + b1) ----
    sgemm_bf<true, true><<<dim3(HIDDEN / 128, MT), 256, SMEM_BF>>>(
        p_agg, p_w1Th, p_w1Tl, p_mid, NN, HIDDEN, DD, p_scale1, p_shift1, b1);

    // ---- out_pre = mid @ W2 (b2 absorbed by BN2) ----
    sgemm_bf<false, false><<<dim3(DD / 128, MT), 256, SMEM_BF>>>(
        p_mid, p_w2Th, p_w2Tl, out, NN, DD, HIDDEN, nullptr, nullptr, nullptr);

    // ---- BN2 stats + in-place apply ----
    col_stats_kernel<<<1024, 128>>>(out, NN, p_stats + 2 * DD, p_stats + 3 * DD);
    bn_finalize_kernel<<<1, DD>>>(p_stats + 2 * DD, p_stats + 3 * DD, bn2_gamma,
                                  bn2_beta, p_scale2, p_shift2, 1.0f / NN);
    bn_apply_kernel<<<(NN * DD + 255) / 256, 256>>>(out, p_scale2, p_shift2);
}